// round 15
// baseline (speedup 1.0000x reference)
#include <cuda_runtime.h>
#include <cstdint>
#include <cstddef>

#define TT 2048
#define BB 64

// 512 MB scratch: precomputed input projections [2][B*T][512]
__device__ float g_zpre[(size_t)2 * BB * TT * 512];

// ---------------- packed f32x2 helpers ----------------
__device__ __forceinline__ unsigned long long pk2(float lo, float hi) {
    unsigned long long r;
    asm("mov.b64 %0, {%1,%2};" : "=l"(r) : "f"(lo), "f"(hi));
    return r;
}
__device__ __forceinline__ void upk2(unsigned long long v, float& lo, float& hi) {
    asm("mov.b64 {%0,%1}, %2;" : "=f"(lo), "=f"(hi) : "l"(v));
}
__device__ __forceinline__ unsigned long long ffma2(unsigned long long a,
                                                    unsigned long long b,
                                                    unsigned long long c) {
    unsigned long long d;
    asm("fma.rn.f32x2 %0, %1, %2, %3;" : "=l"(d) : "l"(a), "l"(b), "l"(c));
    return d;
}
// branchless tanh: 1 - 2/(e^{2x}+1); exact limits, MUFU precision
__device__ __forceinline__ float tanh_f(float x) {
    float e = __expf(2.0f * x);
    return 1.0f - __fdividef(2.0f, e + 1.0f);
}

// ---------------------------------------------------------------------------
// Phase 1: Zpre = x @ W[0:128,:] + b.   (unchanged — proven)
// ---------------------------------------------------------------------------
__global__ void __launch_bounds__(256, 1)
lstm_pre(const float* __restrict__ x,
         const float* __restrict__ W0, const float* __restrict__ bias0,
         const float* __restrict__ W1, const float* __restrict__ bias1) {
    __shared__ float xs[128 * 32];   // [row][k]
    __shared__ float ws[32 * 128];   // [k][col]

    const int dir = blockIdx.z;
    const float* W    = dir ? W1 : W0;
    const float* bias = dir ? bias1 : bias0;
    const size_t m0 = (size_t)blockIdx.y * 128;
    const int    c0 = blockIdx.x * 128;
    const int tid = threadIdx.x;
    const int tx = tid & 31;
    const int ty = tid >> 5;

    unsigned long long acc[16][2];
    #pragma unroll
    for (int i = 0; i < 16; ++i) { acc[i][0] = 0ull; acc[i][1] = 0ull; }

    for (int kc = 0; kc < 4; ++kc) {
        if (kc) __syncthreads();
        #pragma unroll
        for (int i = tid; i < 1024; i += 256) {
            int r = i >> 3, kq = i & 7;
            *(float4*)(xs + r * 32 + kq * 4) =
                *(const float4*)(x + (m0 + r) * 128 + kc * 32 + kq * 4);
        }
        #pragma unroll
        for (int i = tid; i < 1024; i += 256) {
            int k = i >> 5, c4 = (i & 31) * 4;
            *(float4*)(ws + k * 128 + c4) =
                *(const float4*)(W + (size_t)(kc * 32 + k) * 512 + c0 + c4);
        }
        __syncthreads();

        #pragma unroll
        for (int kq = 0; kq < 8; ++kq) {
            float4 av[16];
            #pragma unroll
            for (int i = 0; i < 16; ++i)
                av[i] = *(const float4*)(xs + (ty * 16 + i) * 32 + kq * 4);
            #pragma unroll
            for (int kk = 0; kk < 4; ++kk) {
                ulonglong2 bv = *(const ulonglong2*)(ws + (kq * 4 + kk) * 128 + tx * 4);
                #pragma unroll
                for (int i = 0; i < 16; ++i) {
                    float a = (kk == 0) ? av[i].x : (kk == 1) ? av[i].y
                            : (kk == 2) ? av[i].z : av[i].w;
                    unsigned long long ap = pk2(a, a);
                    acc[i][0] = ffma2(ap, bv.x, acc[i][0]);
                    acc[i][1] = ffma2(ap, bv.y, acc[i][1]);
                }
            }
        }
    }

    float bl0 = bias[c0 + tx * 4 + 0], bl1 = bias[c0 + tx * 4 + 1];
    float bl2 = bias[c0 + tx * 4 + 2], bl3 = bias[c0 + tx * 4 + 3];
    #pragma unroll
    for (int i = 0; i < 16; ++i) {
        float v0, v1, v2, v3;
        upk2(acc[i][0], v0, v1);
        upk2(acc[i][1], v2, v3);
        float4 o = make_float4(v0 + bl0, v1 + bl1, v2 + bl2, v3 + bl3);
        *(float4*)(g_zpre + ((size_t)dir * (BB * TT) + m0 + ty * 16 + i) * 512
                   + c0 + tx * 4) = o;
    }
}

// ---------------------------------------------------------------------------
// Phase 2: recurrence. R13 skeleton (single full-K FMA loop, monotonic-tag
// flag handshake) with shfl-based gates:
//   lane remap: unit ul = w*8 + (lane>>2), gate g = lane&3
//   -> after FMA, each lane applies ITS gate's nonlinearity (parallel exps),
//      8 shfl.sync gather i/j/f/o, g==0 lane updates c and h for (ul).
//   zbuf eliminated; ONE __syncthreads per step (hbuf writes -> next FMA).
// ---------------------------------------------------------------------------
__global__ void __cluster_dims__(2, 1, 1) __launch_bounds__(256, 1)
lstm_rec(const float* __restrict__ Wfw, const float* __restrict__ Wbw,
         float* __restrict__ out) {
    __shared__ __align__(16) float hbuf[2][2][128];  // [parity][row][unit]
    __shared__ __align__(16) uint32_t flags[128];    // [row*64+unit] tags

    uint32_t rank;
    asm("mov.u32 %0, %%cluster_ctarank;" : "=r"(rank));
    const uint32_t peer = rank ^ 1u;
    const int cid = blockIdx.x >> 1;
    const int dir = cid >> 5;
    const int b0  = (cid & 31) * 2;
    const int tid = threadIdx.x;
    const int w   = tid >> 5;
    const int lane = tid & 31;
    const int ul  = w * 8 + (lane >> 2);             // unit within half 0..63
    const int g   = lane & 3;                        // gate 0..3 (i,j,f,o)
    const int col = g * 128 + (int)rank * 64 + ul;   // owned z column
    const float* W = dir ? Wbw : Wfw;

    // W_h column -> registers, packed over k-pairs (rows 128..255 of W)
    unsigned long long w2[64];
    #pragma unroll
    for (int kp = 0; kp < 64; ++kp)
        w2[kp] = pk2(W[(size_t)(128 + 2 * kp) * 512 + col],
                     W[(size_t)(129 + 2 * kp) * 512 + col]);

    for (int i = tid; i < 512; i += 256) ((float*)hbuf)[i] = 0.0f;
    if (tid < 128) flags[tid] = 0u;

    const uint32_t hb_l = (uint32_t)__cvta_generic_to_shared(&hbuf[0][0][0]);
    const uint32_t fl_l = (uint32_t)__cvta_generic_to_shared(&flags[0]);
    uint32_t rm_hb, rm_fl;
    asm("mapa.shared::cluster.u32 %0, %1, %2;" : "=r"(rm_hb) : "r"(hb_l), "r"(peer));
    asm("mapa.shared::cluster.u32 %0, %1, %2;" : "=r"(rm_fl) : "r"(fl_l), "r"(peer));

    // z_pre streaming pointers (rows b0, b0+1)
    const int tq0 = dir ? (TT - 1) : 0;
    const ptrdiff_t dstep = dir ? -512 : 512;
    const float* zp0 = g_zpre + ((size_t)dir * (BB * TT) + (size_t)b0 * TT + tq0) * 512 + col;
    const float* zp1 = zp0 + (size_t)TT * 512;
    float zc0 = __ldcs(zp0), zc1 = __ldcs(zp1);

    // unified gate nonlinearity: s = 1 - bet/(exp(gam*z + del) + 1)
    //   g0 (i): sigm(z)    g1 (j): tanh(z)    g2 (f): sigm(z+1)   g3 (o): sigm(z)
    const float gam = (g == 1) ? 2.0f : 1.0f;
    const float bet = (g == 1) ? 2.0f : 1.0f;
    const float del = (g == 2) ? 1.0f : 0.0f;

    float c0s = 0.0f, c1s = 0.0f;      // cell states (valid on g==0 lanes)
    const int loc_u = (int)rank * 64;

    // per-lane poll slot: lane l watches flags[l*4 .. l*4+3] (covers 128)
    const uint32_t my_fl = fl_l + (uint32_t)(lane * 16);

    __syncthreads();
    // hbuf/flags init visible cluster-wide before any peer DSMEM stores
    asm volatile("barrier.cluster.arrive.aligned;" ::: "memory");
    asm volatile("barrier.cluster.wait.aligned;"   ::: "memory");

    for (int t = 0; t < TT; ++t) {
        const int p  = t & 1;
        const int pn = p ^ 1;

        float zn0 = 0.0f, zn1 = 0.0f;            // prefetch next step's z
        if (t + 1 < TT) {
            zp0 += dstep; zp1 += dstep;
            zn0 = __ldcs(zp0); zn1 = __ldcs(zp1);
        }

        // ---- wait for peer's h of step t-1 (tag >= t) ----
        if (t > 0) {
            const uint32_t need = (uint32_t)t;
            for (;;) {
                uint32_t v0, v1, v2, v3;
                asm volatile("ld.acquire.cluster.shared::cta.u32 %0, [%1];"
                             : "=r"(v0) : "r"(my_fl) : "memory");
                asm volatile("ld.acquire.cluster.shared::cta.u32 %0, [%1];"
                             : "=r"(v1) : "r"(my_fl + 4) : "memory");
                asm volatile("ld.acquire.cluster.shared::cta.u32 %0, [%1];"
                             : "=r"(v2) : "r"(my_fl + 8) : "memory");
                asm volatile("ld.acquire.cluster.shared::cta.u32 %0, [%1];"
                             : "=r"(v3) : "r"(my_fl + 12) : "memory");
                uint32_t mn = min(min(v0, v1), min(v2, v3));
                if (__all_sync(0xffffffffu, mn >= need)) break;
            }
        }

        // ---- z = h @ W_h[:,col]  (R13-exact loop; 2 accumulators) ----
        unsigned long long a0 = 0ull, a1 = 0ull;
        #pragma unroll
        for (int q = 0; q < 32; ++q) {
            ulonglong2 h0 = *(const ulonglong2*)(&hbuf[p][0][q * 4]);
            ulonglong2 h1 = *(const ulonglong2*)(&hbuf[p][1][q * 4]);
            a0 = ffma2(h0.x, w2[2 * q],     a0);
            a0 = ffma2(h0.y, w2[2 * q + 1], a0);
            a1 = ffma2(h1.x, w2[2 * q],     a1);
            a1 = ffma2(h1.y, w2[2 * q + 1], a1);
        }
        float s0l, s0h, s1l, s1h;
        upk2(a0, s0l, s0h);
        upk2(a1, s1l, s1h);
        float z0 = s0l + s0h + zc0;              // this col's z, rows 0/1
        float z1 = s1l + s1h + zc1;
        zc0 = zn0; zc1 = zn1;

        // ---- per-lane gate nonlinearity (all 4 gates' exps in parallel) ----
        float e0 = __expf(fmaf(gam, z0, del));
        float s0 = 1.0f - __fdividef(bet, e0 + 1.0f);
        float e1 = __expf(fmaf(gam, z1, del));
        float s1 = 1.0f - __fdividef(bet, e1 + 1.0f);

        // ---- gather i/j/f/o from adjacent lanes ----
        const int base = lane & ~3;
        float si0 = __shfl_sync(0xffffffffu, s0, base + 0);
        float sj0 = __shfl_sync(0xffffffffu, s0, base + 1);
        float sf0 = __shfl_sync(0xffffffffu, s0, base + 2);
        float so0 = __shfl_sync(0xffffffffu, s0, base + 3);
        float si1 = __shfl_sync(0xffffffffu, s1, base + 0);
        float sj1 = __shfl_sync(0xffffffffu, s1, base + 1);
        float sf1 = __shfl_sync(0xffffffffu, s1, base + 2);
        float so1 = __shfl_sync(0xffffffffu, s1, base + 3);

        if (g == 0) {                            // one lane per unit
            c0s = c0s * sf0 + si0 * sj0;
            c1s = c1s * sf1 + si1 * sj1;
            float h0 = so0 * tanh_f(c0s);
            float h1 = so1 * tanh_f(c1s);

            hbuf[pn][0][loc_u + ul] = h0;        // local half for next step
            hbuf[pn][1][loc_u + ul] = h1;
            if (t < TT - 1) {                    // push to peer + publish tags
                uint32_t o0 = (uint32_t)(((pn * 2 + 0) * 128 + loc_u + ul) * 4);
                uint32_t o1 = (uint32_t)(((pn * 2 + 1) * 128 + loc_u + ul) * 4);
                asm volatile("st.shared::cluster.f32 [%0], %1;"
                             :: "r"(rm_hb + o0), "f"(h0) : "memory");
                asm volatile("st.shared::cluster.f32 [%0], %1;"
                             :: "r"(rm_hb + o1), "f"(h1) : "memory");
                asm volatile("st.release.cluster.shared::cluster.u32 [%0], %1;"
                             :: "r"(rm_fl + (uint32_t)(ul * 4)),
                                "r"((uint32_t)(t + 1)) : "memory");
                asm volatile("st.release.cluster.shared::cluster.u32 [%0], %1;"
                             :: "r"(rm_fl + (uint32_t)((64 + ul) * 4)),
                                "r"((uint32_t)(t + 1)) : "memory");
            }

            const int tq = dir ? (TT - 1 - t) : t;
            out[((size_t)b0 * TT + tq) * 256 + dir * 128 + loc_u + ul]       = h0;
            out[((size_t)(b0 + 1) * TT + tq) * 256 + dir * 128 + loc_u + ul] = h1;
        }
        __syncthreads();                         // hbuf[pn] visible to all warps
    }
}

extern "C" void kernel_launch(void* const* d_in, const int* in_sizes, int n_in,
                              void* d_out, int out_size) {
    const float* x   = (const float*)d_in[0];
    const float* Wfw = (const float*)d_in[1];
    const float* bfw = (const float*)d_in[2];
    const float* Wbw = (const float*)d_in[3];
    const float* bbw = (const float*)d_in[4];
    float* out = (float*)d_out;

    dim3 g1(4, 1024, 2);
    lstm_pre<<<g1, 256>>>(x, Wfw, bfw, Wbw, bbw);
    lstm_rec<<<128, 256>>>(Wfw, Wbw, out);
}

// round 17
// speedup vs baseline: 2.0399x; 2.0399x over previous
#include <cuda_runtime.h>
#include <cuda_bf16.h>
#include <cstdint>
#include <cstddef>

#define TT 2048
#define BB 64
#define LDA 136   // padded bf16 row stride: 272 B -> ldmatrix conflict-free

// 512 MB scratch: precomputed input projections [2][B*T][512]
__device__ float g_zpre[(size_t)2 * BB * TT * 512];

// ---------------- packed f32x2 helpers (rec) ----------------
__device__ __forceinline__ unsigned long long pk2(float lo, float hi) {
    unsigned long long r;
    asm("mov.b64 %0, {%1,%2};" : "=l"(r) : "f"(lo), "f"(hi));
    return r;
}
__device__ __forceinline__ void upk2(unsigned long long v, float& lo, float& hi) {
    asm("mov.b64 {%0,%1}, %2;" : "=f"(lo), "=f"(hi) : "l"(v));
}
__device__ __forceinline__ unsigned long long ffma2(unsigned long long a,
                                                    unsigned long long b,
                                                    unsigned long long c) {
    unsigned long long d;
    asm("fma.rn.f32x2 %0, %1, %2, %3;" : "=l"(d) : "l"(a), "l"(b), "l"(c));
    return d;
}
__device__ __forceinline__ float sigm(float x) {
    return __fdividef(1.0f, 1.0f + __expf(-x));
}
__device__ __forceinline__ float tanh_f(float x) {
    float e = __expf(2.0f * x);
    return 1.0f - __fdividef(2.0f, e + 1.0f);
}
__device__ __forceinline__ uint32_t smem_u32(const void* p) {
    uint32_t a;
    asm("{ .reg .u64 t; cvta.to.shared.u64 t, %1; cvt.u32.u64 %0, t; }"
        : "=r"(a) : "l"(p));
    return a;
}

#define MMA16816(d, a, b)                                                     \
    asm volatile("mma.sync.aligned.m16n8k16.row.col.f32.bf16.bf16.f32 "       \
        "{%0,%1,%2,%3}, {%4,%5,%6,%7}, {%8,%9}, {%0,%1,%2,%3};"               \
        : "+f"((d)[0]), "+f"((d)[1]), "+f"((d)[2]), "+f"((d)[3])              \
        : "r"((a)[0]), "r"((a)[1]), "r"((a)[2]), "r"((a)[3]),                 \
          "r"((b)[0]), "r"((b)[1]))

// smem byte offsets (bf16 elements * 2B); 4 tiles of 128*LDA bf16
#define TILE_B   (128 * LDA * 2)          // 34816 B
#define OFF_AH   0
#define OFF_AL   TILE_B
#define OFF_BH   (2 * TILE_B)
#define OFF_BL   (3 * TILE_B)
#define SM_TOTAL (4 * TILE_B)             // 139264 B

// ---------------------------------------------------------------------------
// Phase 1: Zpre = x @ W[0:128,:] + b  via split-bf16 mma.sync (3 terms).
// grid (4 n-tiles, 1024 m-tiles, 2 dirs), 256 threads, K=128 smem-resident.
// ---------------------------------------------------------------------------
__global__ void __launch_bounds__(256, 1)
lstm_pre_mma(const float* __restrict__ x,
             const float* __restrict__ W0, const float* __restrict__ bias0,
             const float* __restrict__ W1, const float* __restrict__ bias1) {
    extern __shared__ char smem[];
    __nv_bfloat16* Ah = (__nv_bfloat16*)(smem + OFF_AH);  // [m][k]
    __nv_bfloat16* Al = (__nv_bfloat16*)(smem + OFF_AL);
    __nv_bfloat16* Bh = (__nv_bfloat16*)(smem + OFF_BH);  // [k][n]
    __nv_bfloat16* Bl = (__nv_bfloat16*)(smem + OFF_BL);

    const int dir = blockIdx.z;
    const float* W    = dir ? W1 : W0;
    const float* bias = dir ? bias1 : bias0;
    const size_t m0 = (size_t)blockIdx.y * 128;
    const int    c0 = blockIdx.x * 128;
    const int tid = threadIdx.x;
    const int wid = tid >> 5, lane = tid & 31;

    // ---- load + split x tile [128 m][128 k] ----
    for (int i = tid; i < 2048; i += 256) {
        int m = i >> 4, k8 = (i & 15) * 8;
        const float4* s = (const float4*)(x + (m0 + m) * 128 + k8);
        float4 v0 = s[0], v1 = s[1];
        float f[8] = {v0.x, v0.y, v0.z, v0.w, v1.x, v1.y, v1.z, v1.w};
        __align__(16) __nv_bfloat16 hh[8], ll[8];
        #pragma unroll
        for (int j = 0; j < 8; ++j) {
            hh[j] = __float2bfloat16(f[j]);
            ll[j] = __float2bfloat16(f[j] - __bfloat162float(hh[j]));
        }
        *(uint4*)(Ah + m * LDA + k8) = *(const uint4*)hh;
        *(uint4*)(Al + m * LDA + k8) = *(const uint4*)ll;
    }
    // ---- load + split W tile [128 k][128 n] (n contiguous) ----
    for (int i = tid; i < 2048; i += 256) {
        int k = i >> 4, n8 = (i & 15) * 8;
        const float4* s = (const float4*)(W + (size_t)k * 512 + c0 + n8);
        float4 v0 = s[0], v1 = s[1];
        float f[8] = {v0.x, v0.y, v0.z, v0.w, v1.x, v1.y, v1.z, v1.w};
        __align__(16) __nv_bfloat16 hh[8], ll[8];
        #pragma unroll
        for (int j = 0; j < 8; ++j) {
            hh[j] = __float2bfloat16(f[j]);
            ll[j] = __float2bfloat16(f[j] - __bfloat162float(hh[j]));
        }
        *(uint4*)(Bh + k * LDA + n8) = *(const uint4*)hh;
        *(uint4*)(Bl + k * LDA + n8) = *(const uint4*)ll;
    }
    __syncthreads();

    const int wm = (wid >> 2) * 64;      // warp m-offset (2 rows of warps)
    const int wn = (wid & 3) * 32;       // warp n-offset (4 cols of warps)

    float acc[4][4][4];
    #pragma unroll
    for (int mt = 0; mt < 4; ++mt)
        #pragma unroll
        for (int nt = 0; nt < 4; ++nt)
            #pragma unroll
            for (int j = 0; j < 4; ++j) acc[mt][nt][j] = 0.0f;

    const uint32_t sb = smem_u32(smem);
    const uint32_t a_lane_off =
        (uint32_t)(((lane & 15) * LDA + ((lane >> 4) << 3)) * 2);
    const uint32_t b_lane_off = (uint32_t)((lane & 15) * LDA * 2);

    #pragma unroll
    for (int ks = 0; ks < 8; ++ks) {
        const int k0 = ks * 16;
        uint32_t a_h[4][4], a_l[4][4], b_h[4][2], b_l[4][2];

        #pragma unroll
        for (int mt = 0; mt < 4; ++mt) {
            uint32_t ad = sb + OFF_AH + a_lane_off
                        + (uint32_t)(((wm + mt * 16) * LDA + k0) * 2);
            asm volatile("ldmatrix.sync.aligned.m8n8.x4.shared.b16 "
                         "{%0,%1,%2,%3}, [%4];"
                : "=r"(a_h[mt][0]), "=r"(a_h[mt][1]),
                  "=r"(a_h[mt][2]), "=r"(a_h[mt][3]) : "r"(ad));
            asm volatile("ldmatrix.sync.aligned.m8n8.x4.shared.b16 "
                         "{%0,%1,%2,%3}, [%4];"
                : "=r"(a_l[mt][0]), "=r"(a_l[mt][1]),
                  "=r"(a_l[mt][2]), "=r"(a_l[mt][3]) : "r"(ad + TILE_B));
        }
        #pragma unroll
        for (int nt = 0; nt < 4; ++nt) {
            uint32_t bd = sb + OFF_BH + b_lane_off
                        + (uint32_t)((k0 * LDA + wn + nt * 8) * 2);
            asm volatile("ldmatrix.sync.aligned.m8n8.x2.trans.shared.b16 "
                         "{%0,%1}, [%2];"
                : "=r"(b_h[nt][0]), "=r"(b_h[nt][1]) : "r"(bd));
            asm volatile("ldmatrix.sync.aligned.m8n8.x2.trans.shared.b16 "
                         "{%0,%1}, [%2];"
                : "=r"(b_l[nt][0]), "=r"(b_l[nt][1]) : "r"(bd + TILE_B));
        }

        #pragma unroll
        for (int mt = 0; mt < 4; ++mt)
            #pragma unroll
            for (int nt = 0; nt < 4; ++nt) {
                MMA16816(acc[mt][nt], a_h[mt], b_h[nt]);
                MMA16816(acc[mt][nt], a_h[mt], b_l[nt]);
                MMA16816(acc[mt][nt], a_l[mt], b_h[nt]);
            }
    }

    // ---- epilogue: + bias -> g_zpre ----
    const int r0 = lane >> 2;
    const int cB = 2 * (lane & 3);
    #pragma unroll
    for (int nt = 0; nt < 4; ++nt) {
        const int c = c0 + wn + nt * 8 + cB;
        const float bv0 = bias[c], bv1 = bias[c + 1];
        #pragma unroll
        for (int mt = 0; mt < 4; ++mt) {
            size_t row = (size_t)dir * (BB * TT) + m0 + wm + mt * 16 + r0;
            float2 v0 = make_float2(acc[mt][nt][0] + bv0, acc[mt][nt][1] + bv1);
            float2 v1 = make_float2(acc[mt][nt][2] + bv0, acc[mt][nt][3] + bv1);
            *(float2*)(g_zpre + row * 512 + c)       = v0;
            *(float2*)(g_zpre + (row + 8) * 512 + c) = v1;
        }
    }
}

// ---------------------------------------------------------------------------
// Phase 2: recurrence — VERBATIM R13 (best known: flag handshake).
// ---------------------------------------------------------------------------
__global__ void __cluster_dims__(2, 1, 1) __launch_bounds__(256, 1)
lstm_rec(const float* __restrict__ Wfw, const float* __restrict__ Wbw,
         float* __restrict__ out) {
    __shared__ __align__(16) float hbuf[2][2][128];  // [parity][row][unit]
    __shared__ float zbuf[2][256];                   // [row][local col]
    __shared__ __align__(16) uint32_t flags[128];    // [row*64+unit] tags

    uint32_t rank;
    asm("mov.u32 %0, %%cluster_ctarank;" : "=r"(rank));
    const uint32_t peer = rank ^ 1u;
    const int cid = blockIdx.x >> 1;
    const int dir = cid >> 5;
    const int b0  = (cid & 31) * 2;
    const int tid = threadIdx.x;
    const int g   = tid >> 6;
    const int ul  = tid & 63;
    const int col = g * 128 + (int)rank * 64 + ul;
    const float* W = dir ? Wbw : Wfw;

    unsigned long long w2[64];
    #pragma unroll
    for (int kp = 0; kp < 64; ++kp)
        w2[kp] = pk2(W[(size_t)(128 + 2 * kp) * 512 + col],
                     W[(size_t)(129 + 2 * kp) * 512 + col]);

    for (int i = tid; i < 512; i += 256) ((float*)hbuf)[i] = 0.0f;
    if (tid < 128) flags[tid] = 0u;

    const uint32_t hb_l = (uint32_t)__cvta_generic_to_shared(&hbuf[0][0][0]);
    const uint32_t fl_l = (uint32_t)__cvta_generic_to_shared(&flags[0]);
    uint32_t rm_hb, rm_fl;
    asm("mapa.shared::cluster.u32 %0, %1, %2;" : "=r"(rm_hb) : "r"(hb_l), "r"(peer));
    asm("mapa.shared::cluster.u32 %0, %1, %2;" : "=r"(rm_fl) : "r"(fl_l), "r"(peer));

    const int tq0 = dir ? (TT - 1) : 0;
    const ptrdiff_t dstep = dir ? -512 : 512;
    const float* zp0 = g_zpre + ((size_t)dir * (BB * TT) + (size_t)b0 * TT + tq0) * 512 + col;
    const float* zp1 = zp0 + (size_t)TT * 512;
    float zc0 = __ldcs(zp0), zc1 = __ldcs(zp1);

    float c_state = 0.0f;
    const int grow = (tid >> 6) & 1;
    const int gu   = tid & 63;
    const int loc_u = (int)rank * 64;

    const uint32_t my_fl = fl_l + (uint32_t)((tid & 31) * 16);

    __syncthreads();
    asm volatile("barrier.cluster.arrive.aligned;" ::: "memory");
    asm volatile("barrier.cluster.wait.aligned;"   ::: "memory");

    for (int t = 0; t < TT; ++t) {
        const int p  = t & 1;
        const int pn = p ^ 1;

        float zn0 = 0.0f, zn1 = 0.0f;
        if (t + 1 < TT) {
            zp0 += dstep; zp1 += dstep;
            zn0 = __ldcs(zp0); zn1 = __ldcs(zp1);
        }

        if (t > 0) {
            const uint32_t need = (uint32_t)t;
            for (;;) {
                uint32_t v0, v1, v2, v3;
                asm volatile("ld.acquire.cluster.shared::cta.u32 %0, [%1];"
                             : "=r"(v0) : "r"(my_fl) : "memory");
                asm volatile("ld.acquire.cluster.shared::cta.u32 %0, [%1];"
                             : "=r"(v1) : "r"(my_fl + 4) : "memory");
                asm volatile("ld.acquire.cluster.shared::cta.u32 %0, [%1];"
                             : "=r"(v2) : "r"(my_fl + 8) : "memory");
                asm volatile("ld.acquire.cluster.shared::cta.u32 %0, [%1];"
                             : "=r"(v3) : "r"(my_fl + 12) : "memory");
                uint32_t mn = min(min(v0, v1), min(v2, v3));
                if (__all_sync(0xffffffffu, mn >= need)) break;
            }
        }

        unsigned long long a0 = 0ull, a1 = 0ull;
        #pragma unroll
        for (int q = 0; q < 32; ++q) {
            ulonglong2 h0 = *(const ulonglong2*)(&hbuf[p][0][q * 4]);
            ulonglong2 h1 = *(const ulonglong2*)(&hbuf[p][1][q * 4]);
            a0 = ffma2(h0.x, w2[2 * q],     a0);
            a0 = ffma2(h0.y, w2[2 * q + 1], a0);
            a1 = ffma2(h1.x, w2[2 * q],     a1);
            a1 = ffma2(h1.y, w2[2 * q + 1], a1);
        }
        float s0l, s0h, s1l, s1h;
        upk2(a0, s0l, s0h);
        upk2(a1, s1l, s1h);
        zbuf[0][tid] = s0l + s0h + zc0;
        zbuf[1][tid] = s1l + s1h + zc1;
        zc0 = zn0; zc1 = zn1;
        __syncthreads();

        if (tid < 128) {
            float zi = zbuf[grow][gu];
            float zj = zbuf[grow][64  + gu];
            float zf = zbuf[grow][128 + gu];
            float zo = zbuf[grow][192 + gu];
            c_state = c_state * sigm(zf + 1.0f) + sigm(zi) * tanh_f(zj);
            float hn = sigm(zo) * tanh_f(c_state);

            hbuf[pn][grow][loc_u + gu] = hn;
            if (t < TT - 1) {
                uint32_t hoff = (uint32_t)(((pn * 2 + grow) * 128 + loc_u + gu) * 4);
                asm volatile("st.shared::cluster.f32 [%0], %1;"
                             :: "r"(rm_hb + hoff), "f"(hn) : "memory");
                uint32_t foff = (uint32_t)((grow * 64 + gu) * 4);
                asm volatile("st.release.cluster.shared::cluster.u32 [%0], %1;"
                             :: "r"(rm_fl + foff), "r"((uint32_t)(t + 1)) : "memory");
            }

            const int tq = dir ? (TT - 1 - t) : t;
            out[((size_t)(b0 + grow) * TT + tq) * 256 + dir * 128 + loc_u + gu] = hn;
        }
        __syncthreads();
    }
}

extern "C" void kernel_launch(void* const* d_in, const int* in_sizes, int n_in,
                              void* d_out, int out_size) {
    const float* x   = (const float*)d_in[0];
    const float* Wfw = (const float*)d_in[1];
    const float* bfw = (const float*)d_in[2];
    const float* Wbw = (const float*)d_in[3];
    const float* bbw = (const float*)d_in[4];
    float* out = (float*)d_out;

    static int smem_set = 0;
    if (!smem_set) {
        cudaFuncSetAttribute(lstm_pre_mma,
                             cudaFuncAttributeMaxDynamicSharedMemorySize, SM_TOTAL);
        smem_set = 1;
    }

    lstm_pre_mma<<<dim3(4, 1024, 2), 256, SM_TOTAL>>>(x, Wfw, bfw, Wbw, bbw);
    lstm_rec<<<128, 256>>>(Wfw, Wbw, out);
}